// round 1
// baseline (speedup 1.0000x reference)
#include <cuda_runtime.h>
#include <cstdint>

// ---------------- problem constants ----------------
#define B_    16
#define C_    512
#define NSP   400      // spatial positions 20x20
#define HID   256
#define NE    30
#define T_    201
#define OUTD  38       // 30 logits + 8 locs
#define GRU3  768      // 3*HID
#define WIHC  542      // C + NE

// cluster decomposition
#define CSZ   8
#define NPC   (NSP/CSZ)   // 50 attention rows per rank
#define CPC   (C_/CSZ)    // 64 context channels per rank
#define HPC   (HID/CSZ)   // 32 hidden units per rank
#define NTHR  256

// ---------------- device scratch (static, no allocs) ----------------
__device__ float g_hproj[B_ * NSP * HID];   // 6.55 MB
__device__ float g_wihc[GRU3 * C_];         // repacked gru_wih ctx part, aligned rows
__device__ float g_emb[NE * GRU3];          // wih[:,512+e] + bih  (per char, per gate row)

// ---------------- math helpers (deterministic, accurate) ----------------
__device__ __forceinline__ float ex2f_(float x) {
    float y; asm("ex2.approx.f32 %0, %1;" : "=f"(y) : "f"(x)); return y;
}
__device__ __forceinline__ float rcpf_(float x) {
    float y; asm("rcp.approx.f32 %0, %1;" : "=f"(y) : "f"(x)); return y;
}
// tanh(x) = 1 - 2/(1+exp(2x)); exp(2x)=ex2(x*2*log2e). abs err ~1e-7.
__device__ __forceinline__ float tanh_(float x) {
    float u = ex2f_(x * 2.8853900817779268f);
    return fmaf(-2.0f, rcpf_(1.0f + u), 1.0f);
}
__device__ __forceinline__ float sigm_(float x) {
    return rcpf_(1.0f + ex2f_(-x * 1.4426950408889634f));
}
__device__ __forceinline__ float expf_(float x) {
    return ex2f_(x * 1.4426950408889634f);
}

// ---------------- cluster helpers ----------------
#define CLUSTER_SYNC() do { \
    asm volatile("barrier.cluster.arrive.aligned;" ::: "memory"); \
    asm volatile("barrier.cluster.wait.aligned;"   ::: "memory"); \
} while (0)

__device__ __forceinline__ uint32_t s2u_(const void* p) {
    return (uint32_t)__cvta_generic_to_shared(p);
}
__device__ __forceinline__ void st_rank_(float* addr, int rk, float v) {
    uint32_t la = s2u_(addr), ra;
    asm volatile("mapa.shared::cluster.u32 %0, %1, %2;" : "=r"(ra) : "r"(la), "r"(rk));
    asm volatile("st.shared::cluster.f32 [%0], %1;" :: "r"(ra), "f"(v));
}
// all lanes hold v (post warp-reduce); lanes 0..7 push to rank==lane
__device__ __forceinline__ void push8_(float* addr, float v, int lane) {
    if (lane < CSZ) st_rank_(addr, lane, v);
}

__device__ __forceinline__ float wred_(float v) {
#pragma unroll
    for (int o = 16; o; o >>= 1) v += __shfl_xor_sync(0xffffffffu, v, o);
    return v;
}

// warp dot: W row (global, 16B aligned) . x (smem), length = NW*128 floats
template <int NW>
__device__ __forceinline__ float wdot_(const float* __restrict__ Wrow,
                                       const float* __restrict__ x, int lane) {
    const float4* w4 = reinterpret_cast<const float4*>(Wrow);
    const float4* x4 = reinterpret_cast<const float4*>(x);
    float acc = 0.f;
#pragma unroll
    for (int it = 0; it < NW; ++it) {
        float4 wv = w4[lane + 32 * it];
        float4 xv = x4[lane + 32 * it];
        acc = fmaf(wv.x, xv.x, acc); acc = fmaf(wv.y, xv.y, acc);
        acc = fmaf(wv.z, xv.z, acc); acc = fmaf(wv.w, xv.w, acc);
    }
    return wred_(acc);
}

// ---------------- shared layout (all arrays 16B aligned) ----------------
struct __align__(16) SmemT {
    float hp[NPC * HID];    // 51200 B  : this rank's h_proj rows (resident)
    float feat[CPC * NSP];  // 102400 B : this rank's feat channels (resident)
    float hidf[2][HID];     // full hidden, double buffered (pushed by all ranks)
    float ppf[HID];         // full prev_proj
    float m1f[HID];         // full head-1 intermediate (structure)
    float lm1f[HID];        // full head-1 intermediate (loc)
    float ctxf[C_];         // full context
    float eexpf[NSP];       // unnormalized softmax numerators
    float sw[HID];          // score_w
    float esumf[CSZ];       // per-rank partial softmax sums
    float wredbuf[8];       // per-warp partial sums (deterministic reduce)
    float pad[8];
};
#define SMEM_BYTES ((int)sizeof(SmemT))

// ---------------- K0: repack gru_wih ----------------
__global__ void repack_kernel(const float* __restrict__ wih, const float* __restrict__ bih) {
    int g = blockIdx.x;  // 0..767
    for (int c = threadIdx.x; c < C_; c += blockDim.x)
        g_wihc[g * C_ + c] = wih[g * WIHC + c];
    if (threadIdx.x < NE)
        g_emb[threadIdx.x * GRU3 + g] = wih[g * WIHC + C_ + threadIdx.x] + bih[g];
}

// ---------------- K1: h_proj = feat @ i2h_w^T ----------------
__global__ __launch_bounds__(256) void hproj_kernel(const float* __restrict__ fea,
                                                    const float* __restrict__ i2h_w) {
    __shared__ float sf[8 * C_];  // 8 spatial rows x 512 channels
    int b = blockIdx.y, nb = blockIdx.x * 8;
    for (int idx = threadIdx.x; idx < 8 * C_; idx += 256) {
        int q = idx >> 9, c = idx & (C_ - 1);
        sf[idx] = fea[(b * C_ + c) * NSP + nb + q];   // feat[b, nb+q, c]
    }
    __syncthreads();
    int h = threadIdx.x;  // 256 threads = 256 hidden dims
    float acc[8];
#pragma unroll
    for (int q = 0; q < 8; ++q) acc[q] = 0.f;
    const float4* w4 = reinterpret_cast<const float4*>(i2h_w + h * C_);
    for (int c4 = 0; c4 < C_ / 4; ++c4) {
        float4 wv = w4[c4];
#pragma unroll
        for (int q = 0; q < 8; ++q) {
            float4 sv = *reinterpret_cast<const float4*>(sf + q * C_ + c4 * 4);
            acc[q] = fmaf(wv.x, sv.x, acc[q]); acc[q] = fmaf(wv.y, sv.y, acc[q]);
            acc[q] = fmaf(wv.z, sv.z, acc[q]); acc[q] = fmaf(wv.w, sv.w, acc[q]);
        }
    }
#pragma unroll
    for (int q = 0; q < 8; ++q)
        g_hproj[(b * NSP + nb + q) * HID + h] = acc[q];
}

// ---------------- K2: persistent cluster decode ----------------
__global__ __cluster_dims__(CSZ, 1, 1) __launch_bounds__(NTHR, 1)
void decode_kernel(const float* __restrict__ fea,
                   const int*   __restrict__ structure,
                   const float* __restrict__ h2h_w, const float* __restrict__ h2h_b,
                   const float* __restrict__ score_w,
                   const float* __restrict__ whh,   const float* __restrict__ bhh,
                   const float* __restrict__ sg1_w, const float* __restrict__ sg1_b,
                   const float* __restrict__ sg2_w, const float* __restrict__ sg2_b,
                   const float* __restrict__ lg1_w, const float* __restrict__ lg1_b,
                   const float* __restrict__ lg2_w, const float* __restrict__ lg2_b,
                   float* __restrict__ out) {
    extern __shared__ char smraw[];
    SmemT* s = reinterpret_cast<SmemT*>(smraw);

    const int b = blockIdx.y;        // batch
    const int r = blockIdx.x;        // cluster rank (cluster spans grid.x)
    const int tid = threadIdx.x;
    const int lane = tid & 31;
    const int w = tid >> 5;

    // ---- preload resident tiles ----
    for (int idx = tid; idx < NPC * HID; idx += NTHR)
        s->hp[idx] = g_hproj[(b * NSP + r * NPC) * HID + idx];
    for (int idx = tid; idx < CPC * NSP; idx += NTHR)
        s->feat[idx] = fea[(b * C_ + r * CPC) * NSP + idx];
    if (tid < HID) {
        s->sw[tid] = score_w[tid];
        s->hidf[0][tid] = 0.f;
        s->hidf[1][tid] = 0.f;
    }
    __syncthreads();
    CLUSTER_SYNC();

    int cur = 0;
    for (int i = 0; i <= T_; ++i) {
        const int ct = (i < T_) ? structure[b * T_ + i] : 0;
        const float* hid = s->hidf[cur];

        // ===== PHASE 1: prev_proj slice (step i) + head layer-1 slices (step i-1) =====
#pragma unroll
        for (int q = 0; q < 4; ++q) {
            const int row = w * 4 + q;
            const int j = r * HPC + row;   // global row in [0,256)
            if (i < T_) {
                float v = wdot_<2>(h2h_w + j * HID, hid, lane) + h2h_b[j];
                push8_(&s->ppf[j], v, lane);
            }
            if (i >= 1) {
                float m = wdot_<2>(sg1_w + j * HID, hid, lane) + sg1_b[j];
                push8_(&s->m1f[j], m, lane);
                float lm = wdot_<2>(lg1_w + j * HID, hid, lane) + lg1_b[j];
                push8_(&s->lm1f[j], lm, lane);
            }
        }
        CLUSTER_SYNC();

        // ===== PHASE 2: attention scores (step i) + head layer-2 / output (step i-1) =====
        if (i < T_) {
            const float4* pp4 = reinterpret_cast<const float4*>(s->ppf);
            const float4* sw4 = reinterpret_cast<const float4*>(s->sw);
            float4 ppa = pp4[lane], ppb = pp4[lane + 32];
            float4 swa = sw4[lane], swb = sw4[lane + 32];
            float wsum = 0.f;
            for (int nl = w; nl < NPC; nl += 8) {
                const float4* hp4 = reinterpret_cast<const float4*>(s->hp + nl * HID);
                float4 ha = hp4[lane], hb = hp4[lane + 32];
                float acc = 0.f;
                acc = fmaf(tanh_(ha.x + ppa.x), swa.x, acc);
                acc = fmaf(tanh_(ha.y + ppa.y), swa.y, acc);
                acc = fmaf(tanh_(ha.z + ppa.z), swa.z, acc);
                acc = fmaf(tanh_(ha.w + ppa.w), swa.w, acc);
                acc = fmaf(tanh_(hb.x + ppb.x), swb.x, acc);
                acc = fmaf(tanh_(hb.y + ppb.y), swb.y, acc);
                acc = fmaf(tanh_(hb.z + ppb.z), swb.z, acc);
                acc = fmaf(tanh_(hb.w + ppb.w), swb.w, acc);
                acc = wred_(acc);
                float ex = expf_(acc);
                push8_(&s->eexpf[r * NPC + nl], ex, lane);
                wsum += ex;
            }
            if (lane == 0) s->wredbuf[w] = wsum;
        }
        if (i >= 1) {
            int rid = w * 8 + r;   // each (rank,warp) owns at most one output column
            if (rid < OUTD) {
                float val;
                if (rid < NE) {
                    val = wdot_<2>(sg2_w + rid * HID, s->m1f, lane) + sg2_b[rid];
                } else {
                    int lr = rid - NE;
                    val = sigm_(wdot_<2>(lg2_w + lr * HID, s->lm1f, lane) + lg2_b[lr]);
                }
                if (lane == 0) out[(b * T_ + (i - 1)) * OUTD + rid] = val;
            }
        }
        __syncthreads();
        if (i < T_ && tid == 0) {   // deterministic partial-sum push
            float ps = 0.f;
#pragma unroll
            for (int k = 0; k < 8; ++k) ps += s->wredbuf[k];
            for (int k = 0; k < CSZ; ++k) st_rank_(&s->esumf[r], k, ps);
        }
        CLUSTER_SYNC();

        // ===== PHASE 3: softmax normalize + context slice =====
        if (i < T_) {
            float tot = 0.f;
#pragma unroll
            for (int k = 0; k < CSZ; ++k) tot += s->esumf[k];
            const float inv = 1.0f / tot;
            const float4* e4 = reinterpret_cast<const float4*>(s->eexpf);
            for (int cl = w; cl < CPC; cl += 8) {
                const float4* f4 = reinterpret_cast<const float4*>(s->feat + cl * NSP);
                float acc = 0.f;
#pragma unroll
                for (int it = 0; it < 3; ++it) {
                    float4 fv = f4[lane + 32 * it];
                    float4 ev = e4[lane + 32 * it];
                    acc = fmaf(fv.x, ev.x, acc); acc = fmaf(fv.y, ev.y, acc);
                    acc = fmaf(fv.z, ev.z, acc); acc = fmaf(fv.w, ev.w, acc);
                }
                if (lane < 4) {   // tail n = 384..399
                    float4 fv = f4[96 + lane];
                    float4 ev = e4[96 + lane];
                    acc = fmaf(fv.x, ev.x, acc); acc = fmaf(fv.y, ev.y, acc);
                    acc = fmaf(fv.z, ev.z, acc); acc = fmaf(fv.w, ev.w, acc);
                }
                acc = wred_(acc);
                push8_(&s->ctxf[r * CPC + cl], acc * inv, lane);
            }
        }
        CLUSTER_SYNC();

        // ===== PHASE 4: GRU cell for this rank's 32 hidden units =====
        if (i < T_) {
            const float* eb = g_emb + ct * GRU3;
#pragma unroll
            for (int q = 0; q < 4; ++q) {
                const int j = r * HPC + w * 4 + q;
                float gir = wdot_<4>(g_wihc + j * C_,            s->ctxf, lane);
                float giz = wdot_<4>(g_wihc + (HID + j) * C_,    s->ctxf, lane);
                float gin = wdot_<4>(g_wihc + (2 * HID + j) * C_, s->ctxf, lane);
                float ghr = wdot_<2>(whh + j * HID,              hid, lane);
                float ghz = wdot_<2>(whh + (HID + j) * HID,      hid, lane);
                float ghn = wdot_<2>(whh + (2 * HID + j) * HID,  hid, lane);
                gir += eb[j];            ghr += bhh[j];
                giz += eb[HID + j];      ghz += bhh[HID + j];
                gin += eb[2 * HID + j];  ghn += bhh[2 * HID + j];
                float rr = sigm_(gir + ghr);
                float zz = sigm_(giz + ghz);
                float nn = tanh_(fmaf(rr, ghn, gin));
                float hp = hid[j];
                float hn = fmaf(zz, hp - nn, nn);   // (1-z)*n + z*h
                push8_(&s->hidf[cur ^ 1][j], hn, lane);
            }
        }
        CLUSTER_SYNC();
        cur ^= 1;
    }
}

// ---------------- launch ----------------
extern "C" void kernel_launch(void* const* d_in, const int* in_sizes, int n_in,
                              void* d_out, int out_size) {
    const float* fea       = (const float*)d_in[0];
    const int*   structure = (const int*)  d_in[1];
    const float* i2h_w     = (const float*)d_in[2];
    const float* h2h_w     = (const float*)d_in[3];
    const float* h2h_b     = (const float*)d_in[4];
    const float* score_w   = (const float*)d_in[5];
    const float* gru_wih   = (const float*)d_in[6];
    const float* gru_bih   = (const float*)d_in[7];
    const float* gru_whh   = (const float*)d_in[8];
    const float* gru_bhh   = (const float*)d_in[9];
    const float* sg1_w     = (const float*)d_in[10];
    const float* sg1_b     = (const float*)d_in[11];
    const float* sg2_w     = (const float*)d_in[12];
    const float* sg2_b     = (const float*)d_in[13];
    const float* lg1_w     = (const float*)d_in[14];
    const float* lg1_b     = (const float*)d_in[15];
    const float* lg2_w     = (const float*)d_in[16];
    const float* lg2_b     = (const float*)d_in[17];
    float* out = (float*)d_out;

    cudaFuncSetAttribute(decode_kernel,
                         cudaFuncAttributeMaxDynamicSharedMemorySize, SMEM_BYTES);

    repack_kernel<<<GRU3, 256>>>(gru_wih, gru_bih);
    hproj_kernel<<<dim3(NSP / 8, B_), 256>>>(fea, i2h_w);
    decode_kernel<<<dim3(CSZ, B_), NTHR, SMEM_BYTES>>>(
        fea, structure, h2h_w, h2h_b, score_w,
        gru_whh, gru_bhh, sg1_w, sg1_b, sg2_w, sg2_b,
        lg1_w, lg1_b, lg2_w, lg2_b, out);
}

// round 2
// speedup vs baseline: 1.0019x; 1.0019x over previous
#include <cuda_runtime.h>
#include <cstdint>

// ---------------- problem constants ----------------
#define B_    16
#define C_    512
#define NSP   400      // spatial positions 20x20
#define HID   256
#define NE    30
#define T_    201
#define OUTD  38       // 30 logits + 8 locs
#define GRU3  768      // 3*HID
#define WIHC  542      // C + NE

// cluster decomposition
#define CSZ   8
#define NPC   (NSP/CSZ)   // 50 attention rows per rank
#define CPC   (C_/CSZ)    // 64 context channels per rank
#define HPC   (HID/CSZ)   // 32 hidden units per rank
#define NTHR  256

// ---------------- device scratch (static, no allocs) ----------------
__device__ float g_hproj[B_ * NSP * HID];   // 6.55 MB
__device__ float g_wihc[GRU3 * C_];         // repacked gru_wih ctx part, aligned rows
__device__ float g_emb[NE * GRU3];          // wih[:,512+e] + bih  (per char, per gate row)

// ---------------- math helpers (deterministic, accurate) ----------------
__device__ __forceinline__ float ex2f_(float x) {
    float y; asm("ex2.approx.f32 %0, %1;" : "=f"(y) : "f"(x)); return y;
}
__device__ __forceinline__ float rcpf_(float x) {
    float y; asm("rcp.approx.f32 %0, %1;" : "=f"(y) : "f"(x)); return y;
}
// tanh(x) = 1 - 2/(1+exp(2x)); exp(2x)=ex2(x*2*log2e). abs err ~1e-7.
__device__ __forceinline__ float tanh_(float x) {
    float u = ex2f_(x * 2.8853900817779268f);
    return fmaf(-2.0f, rcpf_(1.0f + u), 1.0f);
}
__device__ __forceinline__ float sigm_(float x) {
    return rcpf_(1.0f + ex2f_(-x * 1.4426950408889634f));
}
__device__ __forceinline__ float expf_(float x) {
    return ex2f_(x * 1.4426950408889634f);
}

// ---------------- cluster helpers ----------------
#define CLUSTER_SYNC() do { \
    asm volatile("barrier.cluster.arrive.aligned;" ::: "memory"); \
    asm volatile("barrier.cluster.wait.aligned;"   ::: "memory"); \
} while (0)

__device__ __forceinline__ uint32_t s2u_(const void* p) {
    return (uint32_t)__cvta_generic_to_shared(p);
}
__device__ __forceinline__ void st_rank_(float* addr, int rk, float v) {
    uint32_t la = s2u_(addr), ra;
    asm volatile("mapa.shared::cluster.u32 %0, %1, %2;" : "=r"(ra) : "r"(la), "r"(rk));
    asm volatile("st.shared::cluster.f32 [%0], %1;" :: "r"(ra), "f"(v));
}
// all lanes hold v (post warp-reduce); lanes 0..7 push to rank==lane
__device__ __forceinline__ void push8_(float* addr, float v, int lane) {
    if (lane < CSZ) st_rank_(addr, lane, v);
}

__device__ __forceinline__ float wred_(float v) {
#pragma unroll
    for (int o = 16; o; o >>= 1) v += __shfl_xor_sync(0xffffffffu, v, o);
    return v;
}

// warp dot: W row (global, 16B aligned) . x (smem), length = NW*128 floats
template <int NW>
__device__ __forceinline__ float wdot_(const float* __restrict__ Wrow,
                                       const float* __restrict__ x, int lane) {
    const float4* w4 = reinterpret_cast<const float4*>(Wrow);
    const float4* x4 = reinterpret_cast<const float4*>(x);
    float acc = 0.f;
#pragma unroll
    for (int it = 0; it < NW; ++it) {
        float4 wv = w4[lane + 32 * it];
        float4 xv = x4[lane + 32 * it];
        acc = fmaf(wv.x, xv.x, acc); acc = fmaf(wv.y, xv.y, acc);
        acc = fmaf(wv.z, xv.z, acc); acc = fmaf(wv.w, xv.w, acc);
    }
    return wred_(acc);
}

// ---------------- shared layout (all arrays 16B aligned) ----------------
struct __align__(16) SmemT {
    float hp[NPC * HID];    // 51200 B  : this rank's h_proj rows (resident)
    float feat[CPC * NSP];  // 102400 B : this rank's feat channels (resident)
    float hidf[2][HID];     // full hidden, double buffered (pushed by all ranks)
    float ppf[HID];         // full prev_proj
    float m1f[HID];         // full head-1 intermediate (structure)
    float lm1f[HID];        // full head-1 intermediate (loc)
    float ctxf[C_];         // full context
    float eexpf[NSP];       // unnormalized softmax numerators
    float sw[HID];          // score_w
    float esumf[CSZ];       // per-rank partial softmax sums
    float wredbuf[8];       // per-warp partial sums (deterministic reduce)
    float pad[8];
};
#define SMEM_BYTES ((int)sizeof(SmemT))

// ---------------- K0: repack gru_wih ----------------
__global__ void repack_kernel(const float* __restrict__ wih, const float* __restrict__ bih) {
    int g = blockIdx.x;  // 0..767
    for (int c = threadIdx.x; c < C_; c += blockDim.x)
        g_wihc[g * C_ + c] = wih[g * WIHC + c];
    if (threadIdx.x < NE)
        g_emb[threadIdx.x * GRU3 + g] = wih[g * WIHC + C_ + threadIdx.x] + bih[g];
}

// ---------------- K1: h_proj = feat @ i2h_w^T ----------------
__global__ __launch_bounds__(256) void hproj_kernel(const float* __restrict__ fea,
                                                    const float* __restrict__ i2h_w) {
    __shared__ float sf[8 * C_];  // 8 spatial rows x 512 channels
    int b = blockIdx.y, nb = blockIdx.x * 8;
    for (int idx = threadIdx.x; idx < 8 * C_; idx += 256) {
        int q = idx >> 9, c = idx & (C_ - 1);
        sf[idx] = fea[(b * C_ + c) * NSP + nb + q];   // feat[b, nb+q, c]
    }
    __syncthreads();
    int h = threadIdx.x;  // 256 threads = 256 hidden dims
    float acc[8];
#pragma unroll
    for (int q = 0; q < 8; ++q) acc[q] = 0.f;
    const float4* w4 = reinterpret_cast<const float4*>(i2h_w + h * C_);
    for (int c4 = 0; c4 < C_ / 4; ++c4) {
        float4 wv = w4[c4];
#pragma unroll
        for (int q = 0; q < 8; ++q) {
            float4 sv = *reinterpret_cast<const float4*>(sf + q * C_ + c4 * 4);
            acc[q] = fmaf(wv.x, sv.x, acc[q]); acc[q] = fmaf(wv.y, sv.y, acc[q]);
            acc[q] = fmaf(wv.z, sv.z, acc[q]); acc[q] = fmaf(wv.w, sv.w, acc[q]);
        }
    }
#pragma unroll
    for (int q = 0; q < 8; ++q)
        g_hproj[(b * NSP + nb + q) * HID + h] = acc[q];
}

// ---------------- K2: persistent cluster decode ----------------
__global__ __cluster_dims__(CSZ, 1, 1) __launch_bounds__(NTHR, 1)
void decode_kernel(const float* __restrict__ fea,
                   const int*   __restrict__ structure,
                   const float* __restrict__ h2h_w, const float* __restrict__ h2h_b,
                   const float* __restrict__ score_w,
                   const float* __restrict__ whh,   const float* __restrict__ bhh,
                   const float* __restrict__ sg1_w, const float* __restrict__ sg1_b,
                   const float* __restrict__ sg2_w, const float* __restrict__ sg2_b,
                   const float* __restrict__ lg1_w, const float* __restrict__ lg1_b,
                   const float* __restrict__ lg2_w, const float* __restrict__ lg2_b,
                   float* __restrict__ out) {
    extern __shared__ char smraw[];
    SmemT* s = reinterpret_cast<SmemT*>(smraw);

    const int b = blockIdx.y;        // batch
    const int r = blockIdx.x;        // cluster rank (cluster spans grid.x)
    const int tid = threadIdx.x;
    const int lane = tid & 31;
    const int w = tid >> 5;

    // ---- preload resident tiles ----
    for (int idx = tid; idx < NPC * HID; idx += NTHR)
        s->hp[idx] = g_hproj[(b * NSP + r * NPC) * HID + idx];
    for (int idx = tid; idx < CPC * NSP; idx += NTHR)
        s->feat[idx] = fea[(b * C_ + r * CPC) * NSP + idx];
    if (tid < HID) {
        s->sw[tid] = score_w[tid];
        s->hidf[0][tid] = 0.f;
        s->hidf[1][tid] = 0.f;
    }
    __syncthreads();
    CLUSTER_SYNC();

    int cur = 0;
    for (int i = 0; i <= T_; ++i) {
        const int ct = (i < T_) ? structure[b * T_ + i] : 0;
        const float* hid = s->hidf[cur];

        // ===== PHASE 1: prev_proj slice (step i) + head layer-1 slices (step i-1) =====
#pragma unroll
        for (int q = 0; q < 4; ++q) {
            const int row = w * 4 + q;
            const int j = r * HPC + row;   // global row in [0,256)
            if (i < T_) {
                float v = wdot_<2>(h2h_w + j * HID, hid, lane) + h2h_b[j];
                push8_(&s->ppf[j], v, lane);
            }
            if (i >= 1) {
                float m = wdot_<2>(sg1_w + j * HID, hid, lane) + sg1_b[j];
                push8_(&s->m1f[j], m, lane);
                float lm = wdot_<2>(lg1_w + j * HID, hid, lane) + lg1_b[j];
                push8_(&s->lm1f[j], lm, lane);
            }
        }
        CLUSTER_SYNC();

        // ===== PHASE 2: attention scores (step i) + head layer-2 / output (step i-1) =====
        if (i < T_) {
            const float4* pp4 = reinterpret_cast<const float4*>(s->ppf);
            const float4* sw4 = reinterpret_cast<const float4*>(s->sw);
            float4 ppa = pp4[lane], ppb = pp4[lane + 32];
            float4 swa = sw4[lane], swb = sw4[lane + 32];
            float wsum = 0.f;
            for (int nl = w; nl < NPC; nl += 8) {
                const float4* hp4 = reinterpret_cast<const float4*>(s->hp + nl * HID);
                float4 ha = hp4[lane], hb = hp4[lane + 32];
                float acc = 0.f;
                acc = fmaf(tanh_(ha.x + ppa.x), swa.x, acc);
                acc = fmaf(tanh_(ha.y + ppa.y), swa.y, acc);
                acc = fmaf(tanh_(ha.z + ppa.z), swa.z, acc);
                acc = fmaf(tanh_(ha.w + ppa.w), swa.w, acc);
                acc = fmaf(tanh_(hb.x + ppb.x), swb.x, acc);
                acc = fmaf(tanh_(hb.y + ppb.y), swb.y, acc);
                acc = fmaf(tanh_(hb.z + ppb.z), swb.z, acc);
                acc = fmaf(tanh_(hb.w + ppb.w), swb.w, acc);
                acc = wred_(acc);
                float ex = expf_(acc);
                push8_(&s->eexpf[r * NPC + nl], ex, lane);
                wsum += ex;
            }
            if (lane == 0) s->wredbuf[w] = wsum;
        }
        if (i >= 1) {
            int rid = w * 8 + r;   // each (rank,warp) owns at most one output column
            if (rid < OUTD) {
                float val;
                if (rid < NE) {
                    val = wdot_<2>(sg2_w + rid * HID, s->m1f, lane) + sg2_b[rid];
                } else {
                    int lr = rid - NE;
                    val = sigm_(wdot_<2>(lg2_w + lr * HID, s->lm1f, lane) + lg2_b[lr]);
                }
                if (lane == 0) out[(b * T_ + (i - 1)) * OUTD + rid] = val;
            }
        }
        __syncthreads();
        if (i < T_ && tid == 0) {   // deterministic partial-sum push
            float ps = 0.f;
#pragma unroll
            for (int k = 0; k < 8; ++k) ps += s->wredbuf[k];
            for (int k = 0; k < CSZ; ++k) st_rank_(&s->esumf[r], k, ps);
        }
        CLUSTER_SYNC();

        // ===== PHASE 3: softmax normalize + context slice =====
        if (i < T_) {
            float tot = 0.f;
#pragma unroll
            for (int k = 0; k < CSZ; ++k) tot += s->esumf[k];
            const float inv = 1.0f / tot;
            const float4* e4 = reinterpret_cast<const float4*>(s->eexpf);
            for (int cl = w; cl < CPC; cl += 8) {
                const float4* f4 = reinterpret_cast<const float4*>(s->feat + cl * NSP);
                float acc = 0.f;
#pragma unroll
                for (int it = 0; it < 3; ++it) {
                    float4 fv = f4[lane + 32 * it];
                    float4 ev = e4[lane + 32 * it];
                    acc = fmaf(fv.x, ev.x, acc); acc = fmaf(fv.y, ev.y, acc);
                    acc = fmaf(fv.z, ev.z, acc); acc = fmaf(fv.w, ev.w, acc);
                }
                if (lane < 4) {   // tail n = 384..399
                    float4 fv = f4[96 + lane];
                    float4 ev = e4[96 + lane];
                    acc = fmaf(fv.x, ev.x, acc); acc = fmaf(fv.y, ev.y, acc);
                    acc = fmaf(fv.z, ev.z, acc); acc = fmaf(fv.w, ev.w, acc);
                }
                acc = wred_(acc);
                push8_(&s->ctxf[r * CPC + cl], acc * inv, lane);
            }
        }
        CLUSTER_SYNC();

        // ===== PHASE 4: GRU cell for this rank's 32 hidden units =====
        if (i < T_) {
            const float* eb = g_emb + ct * GRU3;
#pragma unroll
            for (int q = 0; q < 4; ++q) {
                const int j = r * HPC + w * 4 + q;
                float gir = wdot_<4>(g_wihc + j * C_,            s->ctxf, lane);
                float giz = wdot_<4>(g_wihc + (HID + j) * C_,    s->ctxf, lane);
                float gin = wdot_<4>(g_wihc + (2 * HID + j) * C_, s->ctxf, lane);
                float ghr = wdot_<2>(whh + j * HID,              hid, lane);
                float ghz = wdot_<2>(whh + (HID + j) * HID,      hid, lane);
                float ghn = wdot_<2>(whh + (2 * HID + j) * HID,  hid, lane);
                gir += eb[j];            ghr += bhh[j];
                giz += eb[HID + j];      ghz += bhh[HID + j];
                gin += eb[2 * HID + j];  ghn += bhh[2 * HID + j];
                float rr = sigm_(gir + ghr);
                float zz = sigm_(giz + ghz);
                float nn = tanh_(fmaf(rr, ghn, gin));
                float hp = hid[j];
                float hn = fmaf(zz, hp - nn, nn);   // (1-z)*n + z*h
                push8_(&s->hidf[cur ^ 1][j], hn, lane);
            }
        }
        CLUSTER_SYNC();
        cur ^= 1;
    }
}

// ---------------- launch ----------------
extern "C" void kernel_launch(void* const* d_in, const int* in_sizes, int n_in,
                              void* d_out, int out_size) {
    const float* fea       = (const float*)d_in[0];
    const int*   structure = (const int*)  d_in[1];
    const float* i2h_w     = (const float*)d_in[2];
    const float* h2h_w     = (const float*)d_in[3];
    const float* h2h_b     = (const float*)d_in[4];
    const float* score_w   = (const float*)d_in[5];
    const float* gru_wih   = (const float*)d_in[6];
    const float* gru_bih   = (const float*)d_in[7];
    const float* gru_whh   = (const float*)d_in[8];
    const float* gru_bhh   = (const float*)d_in[9];
    const float* sg1_w     = (const float*)d_in[10];
    const float* sg1_b     = (const float*)d_in[11];
    const float* sg2_w     = (const float*)d_in[12];
    const float* sg2_b     = (const float*)d_in[13];
    const float* lg1_w     = (const float*)d_in[14];
    const float* lg1_b     = (const float*)d_in[15];
    const float* lg2_w     = (const float*)d_in[16];
    const float* lg2_b     = (const float*)d_in[17];
    float* out = (float*)d_out;

    cudaFuncSetAttribute(decode_kernel,
                         cudaFuncAttributeMaxDynamicSharedMemorySize, SMEM_BYTES);

    repack_kernel<<<GRU3, 256>>>(gru_wih, gru_bih);
    hproj_kernel<<<dim3(NSP / 8, B_), 256>>>(fea, i2h_w);
    decode_kernel<<<dim3(CSZ, B_), NTHR, SMEM_BYTES>>>(
        fea, structure, h2h_w, h2h_b, score_w,
        gru_whh, gru_bhh, sg1_w, sg1_b, sg2_w, sg2_b,
        lg1_w, lg1_b, lg2_w, lg2_b, out);
}

// round 8
// speedup vs baseline: 1.1639x; 1.1617x over previous
#include <cuda_runtime.h>
#include <cuda_fp16.h>
#include <cstdint>

// ---------------- problem constants ----------------
#define B_    16
#define C_    512
#define NSP   400
#define HID   256
#define NE    30
#define T_    201
#define OUTD  38
#define GRU3  768
#define WIHC  542

#define CSZ   8
#define NPC   (NSP/CSZ)   // 50
#define CPC   (C_/CSZ)    // 64
#define HPC   (HID/CSZ)   // 32
#define NTHR  256

// ---------------- device scratch (static, no allocs) ----------------
__device__ __align__(16) float  g_hproj[B_ * NSP * HID];
__device__ __align__(16) float  g_wihcT[CSZ * C_ * 96];    // [r][c][g=gate*32+jj]
__device__ __align__(16) float  g_whhT [CSZ * HID * 96];   // [r][c][g]
__device__ __align__(16) float  g_h2hT4[CSZ * 64 * 32 * 4];// [r][cb][j][4c]
__device__ __align__(16) __half g_sglgT[CSZ * 64 * 32 * 8];// [r][cb][j][sg:4c | lg:4c]
__device__ __align__(16) float  g_emb  [NE * GRU3];        // wih[:,512+e]+bih

// ---------------- math helpers ----------------
__device__ __forceinline__ float ex2f_(float x) {
    float y; asm("ex2.approx.f32 %0, %1;" : "=f"(y) : "f"(x)); return y;
}
__device__ __forceinline__ float rcpf_(float x) {
    float y; asm("rcp.approx.f32 %0, %1;" : "=f"(y) : "f"(x)); return y;
}
__device__ __forceinline__ float tanh_(float x) {        // accurate: 1-2/(1+e^2x)
    float u = ex2f_(x * 2.8853900817779268f);
    return fmaf(-2.0f, rcpf_(1.0f + u), 1.0f);
}
__device__ __forceinline__ float sigm_(float x) {
    return rcpf_(1.0f + ex2f_(-x * 1.4426950408889634f));
}
__device__ __forceinline__ float expf_(float x) {
    return ex2f_(x * 1.4426950408889634f);
}

// ---------------- cluster helpers ----------------
#define CLUSTER_SYNC() do { \
    asm volatile("barrier.cluster.arrive.aligned;" ::: "memory"); \
    asm volatile("barrier.cluster.wait.aligned;"   ::: "memory"); \
} while (0)

__device__ __forceinline__ uint32_t s2u_(const void* p) {
    return (uint32_t)__cvta_generic_to_shared(p);
}
__device__ __forceinline__ void st_rank_(float* addr, int rk, float v) {
    uint32_t la = s2u_(addr), ra;
    asm volatile("mapa.shared::cluster.u32 %0, %1, %2;" : "=r"(ra) : "r"(la), "r"(rk));
    asm volatile("st.shared::cluster.f32 [%0], %1;" :: "r"(ra), "f"(v));
}
__device__ __forceinline__ void push8_(float* addr, float v, int lane) {
    if (lane < CSZ) st_rank_(addr, lane, v);
}
__device__ __forceinline__ float wred_(float v) {
#pragma unroll
    for (int o = 16; o; o >>= 1) v += __shfl_xor_sync(0xffffffffu, v, o);
    return v;
}
template <int NW>
__device__ __forceinline__ float wdot_(const float* __restrict__ Wrow,
                                       const float* __restrict__ x, int lane) {
    const float4* w4 = reinterpret_cast<const float4*>(Wrow);
    const float4* x4 = reinterpret_cast<const float4*>(x);
    float acc = 0.f;
#pragma unroll
    for (int it = 0; it < NW; ++it) {
        float4 wv = w4[lane + 32 * it];
        float4 xv = x4[lane + 32 * it];
        acc = fmaf(wv.x, xv.x, acc); acc = fmaf(wv.y, xv.y, acc);
        acc = fmaf(wv.z, xv.z, acc); acc = fmaf(wv.w, xv.w, acc);
    }
    return wred_(acc);
}

// ---------------- shared layout ----------------
struct __align__(16) SmemT {
    float hp[NPC * HID];     // 51200 B resident h_proj rows
    float whhT[HID * 96];    // 98304 B resident GRU hh weights (transposed)
    float sg2s[NE * HID];    // 30720 B resident head-L2 weights
    float lg2s[8 * HID];     // 8192 B
    float hidf[2][HID];
    float ppf[HID];
    float m1f[HID];
    float lm1f[HID];
    float ctxf[C_];
    float eexpf[NSP];
    float sw[HID];
    float partA[8 * 96];
    float partB[8 * 96];
    float pb1[96];           // [h2h_b | sg1_b | lg1_b] rank slices
    float pbg[96];           // bhh in g-order
    float esumf[CSZ];
    float wredbuf[8];
    int   stok[T_ + 3];      // structure tokens for this batch
    float pad[8];
};
#define SMEM_BYTES ((int)sizeof(SmemT))

// ---------------- K0a: transpose/repack weights ----------------
__global__ void repackT_kernel(const float* __restrict__ h2h_w,
                               const float* __restrict__ sg1_w,
                               const float* __restrict__ lg1_w,
                               const float* __restrict__ whh,
                               const float* __restrict__ wih) {
    int r = blockIdx.x, c = blockIdx.y, t = threadIdx.x;  // t < 96
    {
        int gate = t >> 5, jj = t & 31;
        int row = gate * HID + r * HPC + jj;
        g_wihcT[(r * C_ + c) * 96 + t] = wih[row * WIHC + c];
        if (c < HID)
            g_whhT[(r * HID + c) * 96 + t] = whh[row * HID + c];
    }
    if (c < HID) {
        if (t < 32)
            g_h2hT4[((r * 64 + (c >> 2)) * 32 + t) * 4 + (c & 3)] =
                h2h_w[(r * HPC + t) * HID + c];
        if (t < 64) {
            int j = t & 31;
            float v = (t < 32) ? sg1_w[(r * HPC + j) * HID + c]
                               : lg1_w[(r * HPC + j) * HID + c];
            // [r][cb][j][ (sg=0|lg=1)*4 + c&3 ]
            g_sglgT[((r * 64 + (c >> 2)) * 32 + j) * 8 + (t >> 5) * 4 + (c & 3)] =
                __float2half(v);
        }
    }
}

// ---------------- K0b: embedding fold ----------------
__global__ void emb_kernel(const float* __restrict__ wih, const float* __restrict__ bih) {
    int row = blockIdx.x;
    if (threadIdx.x < NE)
        g_emb[threadIdx.x * GRU3 + row] = wih[row * WIHC + C_ + threadIdx.x] + bih[row];
}

// ---------------- K1: h_proj = feat @ i2h_w^T ----------------
__global__ __launch_bounds__(256) void hproj_kernel(const float* __restrict__ fea,
                                                    const float* __restrict__ i2h_w) {
    __shared__ float sf[8 * C_];
    int b = blockIdx.y, nb = blockIdx.x * 8;
    for (int idx = threadIdx.x; idx < 8 * C_; idx += 256) {
        int q = idx >> 9, c = idx & (C_ - 1);
        sf[idx] = fea[(b * C_ + c) * NSP + nb + q];
    }
    __syncthreads();
    int h = threadIdx.x;
    float acc[8];
#pragma unroll
    for (int q = 0; q < 8; ++q) acc[q] = 0.f;
    const float4* w4 = reinterpret_cast<const float4*>(i2h_w + h * C_);
    for (int c4 = 0; c4 < C_ / 4; ++c4) {
        float4 wv = w4[c4];
#pragma unroll
        for (int q = 0; q < 8; ++q) {
            float4 sv = *reinterpret_cast<const float4*>(sf + q * C_ + c4 * 4);
            acc[q] = fmaf(wv.x, sv.x, acc[q]); acc[q] = fmaf(wv.y, sv.y, acc[q]);
            acc[q] = fmaf(wv.z, sv.z, acc[q]); acc[q] = fmaf(wv.w, sv.w, acc[q]);
        }
    }
#pragma unroll
    for (int q = 0; q < 8; ++q)
        g_hproj[(b * NSP + nb + q) * HID + h] = acc[q];
}

// ---------------- K2: persistent cluster decode ----------------
__global__ __cluster_dims__(CSZ, 1, 1) __launch_bounds__(NTHR, 1)
void decode_kernel(const float* __restrict__ fea,
                   const int*   __restrict__ structure,
                   const float* __restrict__ h2h_b,
                   const float* __restrict__ score_w,
                   const float* __restrict__ bhh,
                   const float* __restrict__ sg1_b,
                   const float* __restrict__ sg2_w, const float* __restrict__ sg2_b,
                   const float* __restrict__ lg1_b,
                   const float* __restrict__ lg2_w, const float* __restrict__ lg2_b,
                   float* __restrict__ out) {
    extern __shared__ char smraw[];
    SmemT* s = reinterpret_cast<SmemT*>(smraw);

    const int b = blockIdx.y;
    const int r = blockIdx.x;
    const int tid = threadIdx.x;
    const int lane = tid & 31;
    const int w = tid >> 5;

    // ---- preload resident tiles ----
    for (int idx = tid; idx < NPC * HID; idx += NTHR)
        s->hp[idx] = g_hproj[(b * NSP + r * NPC) * HID + idx];
    for (int idx = tid; idx < HID * 96; idx += NTHR)
        s->whhT[idx] = g_whhT[r * HID * 96 + idx];
    for (int idx = tid; idx < NE * HID; idx += NTHR)
        s->sg2s[idx] = sg2_w[idx];
    for (int idx = tid; idx < 8 * HID; idx += NTHR)
        s->lg2s[idx] = lg2_w[idx];
    for (int idx = tid; idx < T_; idx += NTHR)
        s->stok[idx] = structure[b * T_ + idx];
    if (tid < HID) {
        s->sw[tid] = score_w[tid];
        s->hidf[0][tid] = 0.f;
        s->hidf[1][tid] = 0.f;
    }
    if (tid < 96) {
        s->pb1[tid] = (tid < 32) ? h2h_b[r * HPC + tid]
                    : (tid < 64) ? sg1_b[r * HPC + tid - 32]
                                 : lg1_b[r * HPC + tid - 64];
        s->pbg[tid] = bhh[(tid >> 5) * HID + r * HPC + (tid & 31)];
    }
    __syncthreads();
    CLUSTER_SYNC();

    // hoisted attention score weights
    const float4* sw4 = reinterpret_cast<const float4*>(s->sw);
    const float4 swa = sw4[lane], swb = sw4[lane + 32];

    int cur = 0;
    for (int i = 0; i <= T_; ++i) {
        const float* hid = s->hidf[cur];

        // prefetch embedding biases for PH4 (consumed 3 phases later)
        float ebr = 0.f, ebz = 0.f, ebn = 0.f;
        if (i < T_ && tid < HPC) {
            const int ct = s->stok[i];
            const float* eb = g_emb + ct * GRU3 + r * HPC + tid;
            ebr = eb[0]; ebz = eb[HID]; ebn = eb[2 * HID];
        }

        // ===== PH1: pp + head-L1 via transposed weights (c-split, no shfl) =====
        {
            float accp = 0.f, acc0 = 0.f, acc1 = 0.f;
            const float4* h2h4 = reinterpret_cast<const float4*>(g_h2hT4)
                                 + (r * 64 + w * 8) * 32 + lane;
            const uint4* sg4 = reinterpret_cast<const uint4*>(g_sglgT)
                               + (r * 64 + w * 8) * 32 + lane;
#pragma unroll
            for (int q = 0; q < 8; ++q) {
                float4 xv = *reinterpret_cast<const float4*>(hid + (w * 8 + q) * 4);
                float4 wv = h2h4[q * 32];
                accp = fmaf(wv.x, xv.x, accp); accp = fmaf(wv.y, xv.y, accp);
                accp = fmaf(wv.z, xv.z, accp); accp = fmaf(wv.w, xv.w, accp);
                uint4 sv = sg4[q * 32];
                float2 a0 = __half22float2(*reinterpret_cast<const __half2*>(&sv.x));
                float2 a1 = __half22float2(*reinterpret_cast<const __half2*>(&sv.y));
                float2 b0 = __half22float2(*reinterpret_cast<const __half2*>(&sv.z));
                float2 b1 = __half22float2(*reinterpret_cast<const __half2*>(&sv.w));
                acc0 = fmaf(a0.x, xv.x, acc0); acc0 = fmaf(a0.y, xv.y, acc0);
                acc0 = fmaf(a1.x, xv.z, acc0); acc0 = fmaf(a1.y, xv.w, acc0);
                acc1 = fmaf(b0.x, xv.x, acc1); acc1 = fmaf(b0.y, xv.y, acc1);
                acc1 = fmaf(b1.x, xv.z, acc1); acc1 = fmaf(b1.y, xv.w, acc1);
            }
            s->partA[w * 96 + lane]      = accp;   // pp partial, j=lane
            s->partA[w * 96 + 32 + lane] = acc0;   // sg1 partial, j=lane
            s->partA[w * 96 + 64 + lane] = acc1;   // lg1 partial, j=lane
        }
        __syncthreads();
        if (tid < 96) {
            float v = s->pb1[tid];
#pragma unroll
            for (int k = 0; k < 8; ++k) v += s->partA[k * 96 + tid];
            float* dst = (tid < 32) ? &s->ppf[r * HPC + tid]
                       : (tid < 64) ? &s->m1f[r * HPC + tid - 32]
                                    : &s->lm1f[r * HPC + tid - 64];
#pragma unroll
            for (int k = 0; k < CSZ; ++k) st_rank_(dst, k, v);
        }
        CLUSTER_SYNC();

        // ===== PH2: attention scores (i<T) + head-L2 output (i>=1) =====
        if (i < T_) {
            const float4* pp4 = reinterpret_cast<const float4*>(s->ppf);
            float4 ppa = pp4[lane], ppb = pp4[lane + 32];
            float wsum = 0.f;
            for (int nl = w; nl < NPC; nl += 8) {
                const float4* hp4 = reinterpret_cast<const float4*>(s->hp + nl * HID);
                float4 ha = hp4[lane], hb = hp4[lane + 32];
                float acc = 0.f;
                acc = fmaf(tanh_(ha.x + ppa.x), swa.x, acc);
                acc = fmaf(tanh_(ha.y + ppa.y), swa.y, acc);
                acc = fmaf(tanh_(ha.z + ppa.z), swa.z, acc);
                acc = fmaf(tanh_(ha.w + ppa.w), swa.w, acc);
                acc = fmaf(tanh_(hb.x + ppb.x), swb.x, acc);
                acc = fmaf(tanh_(hb.y + ppb.y), swb.y, acc);
                acc = fmaf(tanh_(hb.z + ppb.z), swb.z, acc);
                acc = fmaf(tanh_(hb.w + ppb.w), swb.w, acc);
                acc = wred_(acc);
                float ex = expf_(acc);
                push8_(&s->eexpf[r * NPC + nl], ex, lane);
                wsum += ex;
            }
            if (lane == 0) s->wredbuf[w] = wsum;
        }
        if (i >= 1) {
            int rid = w * 8 + r;
            if (rid < OUTD) {
                float val;
                if (rid < NE) {
                    val = wdot_<2>(s->sg2s + rid * HID, s->m1f, lane) + sg2_b[rid];
                } else {
                    int lr = rid - NE;
                    val = sigm_(wdot_<2>(s->lg2s + lr * HID, s->lm1f, lane) + lg2_b[lr]);
                }
                if (lane == 0) out[(b * T_ + (i - 1)) * OUTD + rid] = val;
            }
        }
        __syncthreads();
        if (i < T_ && tid == 0) {
            float ps = 0.f;
#pragma unroll
            for (int k = 0; k < 8; ++k) ps += s->wredbuf[k];
            for (int k = 0; k < CSZ; ++k) st_rank_(&s->esumf[r], k, ps);
        }
        CLUSTER_SYNC();

        // ===== PH3: softmax normalize + context (feat streamed from L2) =====
        if (i < T_) {
            float tot = 0.f;
#pragma unroll
            for (int k = 0; k < CSZ; ++k) tot += s->esumf[k];
            const float inv = 1.0f / tot;
            const float4* e4 = reinterpret_cast<const float4*>(s->eexpf);
            const float* fbase = fea + (b * C_ + r * CPC) * NSP;
            for (int cl = w; cl < CPC; cl += 8) {
                const float4* f4 = reinterpret_cast<const float4*>(fbase + cl * NSP);
                float acc = 0.f;
#pragma unroll
                for (int it = 0; it < 3; ++it) {
                    float4 fv = f4[lane + 32 * it];
                    float4 ev = e4[lane + 32 * it];
                    acc = fmaf(fv.x, ev.x, acc); acc = fmaf(fv.y, ev.y, acc);
                    acc = fmaf(fv.z, ev.z, acc); acc = fmaf(fv.w, ev.w, acc);
                }
                if (lane < 4) {
                    float4 fv = f4[96 + lane];
                    float4 ev = e4[96 + lane];
                    acc = fmaf(fv.x, ev.x, acc); acc = fmaf(fv.y, ev.y, acc);
                    acc = fmaf(fv.z, ev.z, acc); acc = fmaf(fv.w, ev.w, acc);
                }
                acc = wred_(acc);
                push8_(&s->ctxf[r * CPC + cl], acc * inv, lane);
            }
        }
        CLUSTER_SYNC();

        // ===== PH4: GRU (gi streamed wihcT, gh resident whhT; no shfl) =====
        if (i < T_) {
            if (lane < 24) {
                float4 ga = make_float4(0.f, 0.f, 0.f, 0.f);
                const float4* wi4 = reinterpret_cast<const float4*>(
                                        g_wihcT + (r * C_ + w * 64) * 96) + lane;
#pragma unroll 4
                for (int c4 = 0; c4 < 16; ++c4) {
                    float4 xv = *reinterpret_cast<const float4*>(s->ctxf + w * 64 + c4 * 4);
                    float4 w0 = wi4[(c4 * 4 + 0) * 24];
                    float4 w1 = wi4[(c4 * 4 + 1) * 24];
                    float4 w2 = wi4[(c4 * 4 + 2) * 24];
                    float4 w3 = wi4[(c4 * 4 + 3) * 24];
                    ga.x = fmaf(w0.x, xv.x, ga.x); ga.y = fmaf(w0.y, xv.x, ga.y);
                    ga.z = fmaf(w0.z, xv.x, ga.z); ga.w = fmaf(w0.w, xv.x, ga.w);
                    ga.x = fmaf(w1.x, xv.y, ga.x); ga.y = fmaf(w1.y, xv.y, ga.y);
                    ga.z = fmaf(w1.z, xv.y, ga.z); ga.w = fmaf(w1.w, xv.y, ga.w);
                    ga.x = fmaf(w2.x, xv.z, ga.x); ga.y = fmaf(w2.y, xv.z, ga.y);
                    ga.z = fmaf(w2.z, xv.z, ga.z); ga.w = fmaf(w2.w, xv.z, ga.w);
                    ga.x = fmaf(w3.x, xv.w, ga.x); ga.y = fmaf(w3.y, xv.w, ga.y);
                    ga.z = fmaf(w3.z, xv.w, ga.z); ga.w = fmaf(w3.w, xv.w, ga.w);
                }
                *reinterpret_cast<float4*>(&s->partA[w * 96 + 4 * lane]) = ga;

                float4 gb = make_float4(0.f, 0.f, 0.f, 0.f);
#pragma unroll 4
                for (int c4 = 0; c4 < 8; ++c4) {
                    float4 xv = *reinterpret_cast<const float4*>(hid + w * 32 + c4 * 4);
                    float4 w0 = *reinterpret_cast<const float4*>(&s->whhT[(w * 32 + c4 * 4 + 0) * 96 + 4 * lane]);
                    float4 w1 = *reinterpret_cast<const float4*>(&s->whhT[(w * 32 + c4 * 4 + 1) * 96 + 4 * lane]);
                    float4 w2 = *reinterpret_cast<const float4*>(&s->whhT[(w * 32 + c4 * 4 + 2) * 96 + 4 * lane]);
                    float4 w3 = *reinterpret_cast<const float4*>(&s->whhT[(w * 32 + c4 * 4 + 3) * 96 + 4 * lane]);
                    gb.x = fmaf(w0.x, xv.x, gb.x); gb.y = fmaf(w0.y, xv.x, gb.y);
                    gb.z = fmaf(w0.z, xv.x, gb.z); gb.w = fmaf(w0.w, xv.x, gb.w);
                    gb.x = fmaf(w1.x, xv.y, gb.x); gb.y = fmaf(w1.y, xv.y, gb.y);
                    gb.z = fmaf(w1.z, xv.y, gb.z); gb.w = fmaf(w1.w, xv.y, gb.w);
                    gb.x = fmaf(w2.x, xv.z, gb.x); gb.y = fmaf(w2.y, xv.z, gb.y);
                    gb.z = fmaf(w2.z, xv.z, gb.z); gb.w = fmaf(w2.w, xv.z, gb.w);
                    gb.x = fmaf(w3.x, xv.w, gb.x); gb.y = fmaf(w3.y, xv.w, gb.y);
                    gb.z = fmaf(w3.z, xv.w, gb.z); gb.w = fmaf(w3.w, xv.w, gb.w);
                }
                *reinterpret_cast<float4*>(&s->partB[w * 96 + 4 * lane]) = gb;
            }
            __syncthreads();
            if (tid < HPC) {
                float gir = 0.f, giz = 0.f, gin = 0.f, ghr = 0.f, ghz = 0.f, ghn = 0.f;
#pragma unroll
                for (int k = 0; k < 8; ++k) {
                    gir += s->partA[k * 96 + tid];
                    giz += s->partA[k * 96 + 32 + tid];
                    gin += s->partA[k * 96 + 64 + tid];
                    ghr += s->partB[k * 96 + tid];
                    ghz += s->partB[k * 96 + 32 + tid];
                    ghn += s->partB[k * 96 + 64 + tid];
                }
                gir += ebr;
                giz += ebz;
                gin += ebn;
                ghr += s->pbg[tid];
                ghz += s->pbg[32 + tid];
                ghn += s->pbg[64 + tid];
                float rr = sigm_(gir + ghr);
                float zz = sigm_(giz + ghz);
                float nn = tanh_(fmaf(rr, ghn, gin));
                float hn = fmaf(zz, hid[r * HPC + tid] - nn, nn);
                float* dst = &s->hidf[cur ^ 1][r * HPC + tid];
#pragma unroll
                for (int k = 0; k < CSZ; ++k) st_rank_(dst, k, hn);
            }
        }
        CLUSTER_SYNC();
        cur ^= 1;
    }
}

// ---------------- launch ----------------
extern "C" void kernel_launch(void* const* d_in, const int* in_sizes, int n_in,
                              void* d_out, int out_size) {
    const float* fea       = (const float*)d_in[0];
    const int*   structure = (const int*)  d_in[1];
    const float* i2h_w     = (const float*)d_in[2];
    const float* h2h_w     = (const float*)d_in[3];
    const float* h2h_b     = (const float*)d_in[4];
    const float* score_w   = (const float*)d_in[5];
    const float* gru_wih   = (const float*)d_in[6];
    const float* gru_bih   = (const float*)d_in[7];
    const float* gru_whh   = (const float*)d_in[8];
    const float* gru_bhh   = (const float*)d_in[9];
    const float* sg1_w     = (const float*)d_in[10];
    const float* sg1_b     = (const float*)d_in[11];
    const float* sg2_w     = (const float*)d_in[12];
    const float* sg2_b     = (const float*)d_in[13];
    const float* lg1_w     = (const float*)d_in[14];
    const float* lg1_b     = (const float*)d_in[15];
    const float* lg2_w     = (const float*)d_in[16];
    const float* lg2_b     = (const float*)d_in[17];
    float* out = (float*)d_out;

    cudaFuncSetAttribute(decode_kernel,
                         cudaFuncAttributeMaxDynamicSharedMemorySize, SMEM_BYTES);

    repackT_kernel<<<dim3(CSZ, C_), 96>>>(h2h_w, sg1_w, lg1_w, gru_whh, gru_wih);
    emb_kernel<<<GRU3, 32>>>(gru_wih, gru_bih);
    hproj_kernel<<<dim3(NSP / 8, B_), 256>>>(fea, i2h_w);
    decode_kernel<<<dim3(CSZ, B_), NTHR, SMEM_BYTES>>>(
        fea, structure, h2h_b, score_w, gru_bhh,
        sg1_b, sg2_w, sg2_b, lg1_b, lg2_w, lg2_b, out);
}

// round 9
// speedup vs baseline: 1.4081x; 1.2098x over previous
#include <cuda_runtime.h>
#include <cuda_fp16.h>
#include <cstdint>

// ---------------- problem constants ----------------
#define B_    16
#define C_    512
#define NSP   400
#define HID   256
#define NE    30
#define T_    201
#define OUTD  38
#define GRU3  768
#define WIHC  542

#define CSZ   8
#define NPC   (NSP/CSZ)   // 50
#define CPC   (C_/CSZ)    // 64
#define HPC   (HID/CSZ)   // 32
#define NTHR  512
#define NWRP  16

// ---------------- device scratch (static, no allocs) ----------------
__device__ __align__(16) float  g_hproj[B_ * NSP * HID];
__device__ __align__(16) __half g_wihcTh[CSZ * C_ * 96];   // [r][c][g]  f16
__device__ __align__(16) float  g_whhT [CSZ * HID * 96];   // [r][c][g]
__device__ __align__(16) float  g_h2hT4[CSZ * 64 * 32 * 4];// [r][cb][j][4c]
__device__ __align__(16) __half g_sglgT[CSZ * 64 * 32 * 8];// [r][cb][j][sg:4c | lg:4c]
__device__ __align__(16) float  g_emb  [NE * GRU3];        // wih[:,512+e]+bih

// ---------------- math helpers ----------------
__device__ __forceinline__ float ex2f_(float x) {
    float y; asm("ex2.approx.f32 %0, %1;" : "=f"(y) : "f"(x)); return y;
}
__device__ __forceinline__ float rcpf_(float x) {
    float y; asm("rcp.approx.f32 %0, %1;" : "=f"(y) : "f"(x)); return y;
}
__device__ __forceinline__ float tanh_(float x) {        // accurate: 1-2/(1+e^2x)
    float u = ex2f_(x * 2.8853900817779268f);
    return fmaf(-2.0f, rcpf_(1.0f + u), 1.0f);
}
__device__ __forceinline__ float sigm_(float x) {
    return rcpf_(1.0f + ex2f_(-x * 1.4426950408889634f));
}
__device__ __forceinline__ float expf_(float x) {
    return ex2f_(x * 1.4426950408889634f);
}

// ---------------- cluster helpers ----------------
#define CLUSTER_SYNC() do { \
    asm volatile("barrier.cluster.arrive.aligned;" ::: "memory"); \
    asm volatile("barrier.cluster.wait.aligned;"   ::: "memory"); \
} while (0)

__device__ __forceinline__ uint32_t s2u_(const void* p) {
    return (uint32_t)__cvta_generic_to_shared(p);
}
__device__ __forceinline__ void st_rank_(float* addr, int rk, float v) {
    uint32_t la = s2u_(addr), ra;
    asm volatile("mapa.shared::cluster.u32 %0, %1, %2;" : "=r"(ra) : "r"(la), "r"(rk));
    asm volatile("st.shared::cluster.f32 [%0], %1;" :: "r"(ra), "f"(v));
}
__device__ __forceinline__ void push8_(float* addr, float v, int lane) {
    if (lane < CSZ) st_rank_(addr, lane, v);
}
__device__ __forceinline__ float wred_(float v) {
#pragma unroll
    for (int o = 16; o; o >>= 1) v += __shfl_xor_sync(0xffffffffu, v, o);
    return v;
}
template <int NW>
__device__ __forceinline__ float wdot_(const float* __restrict__ Wrow,
                                       const float* __restrict__ x, int lane) {
    const float4* w4 = reinterpret_cast<const float4*>(Wrow);
    const float4* x4 = reinterpret_cast<const float4*>(x);
    float acc = 0.f;
#pragma unroll
    for (int it = 0; it < NW; ++it) {
        float4 wv = w4[lane + 32 * it];
        float4 xv = x4[lane + 32 * it];
        acc = fmaf(wv.x, xv.x, acc); acc = fmaf(wv.y, xv.y, acc);
        acc = fmaf(wv.z, xv.z, acc); acc = fmaf(wv.w, xv.w, acc);
    }
    return wred_(acc);
}

// ---------------- shared layout ----------------
struct __align__(16) SmemT {
    float hp[NPC * HID];     // 51200 B resident h_proj rows
    float whhT[HID * 96];    // 98304 B resident GRU hh weights (transposed)
    float sg2s[NE * HID];    // 30720 B resident head-L2 weights
    float lg2s[8 * HID];     // 8192 B
    float hidf[2][HID];
    float ppf[HID];
    float m1f[HID];
    float lm1f[HID];
    float ctxf[C_];
    float eexpf[NSP];
    float sw[HID];
    float partA[NWRP * 96];
    float partB[NWRP * 96];
    float pb1[96];           // [h2h_b | sg1_b | lg1_b] rank slices
    float pbg[96];           // bhh in g-order
    float esumf[CSZ];
    float wredbuf[NWRP];
    int   stok[T_ + 3];      // structure tokens for this batch
    float pad[8];
};
#define SMEM_BYTES ((int)sizeof(SmemT))

// ---------------- K0a: transpose/repack weights ----------------
__global__ void repackT_kernel(const float* __restrict__ h2h_w,
                               const float* __restrict__ sg1_w,
                               const float* __restrict__ lg1_w,
                               const float* __restrict__ whh,
                               const float* __restrict__ wih) {
    int r = blockIdx.x, c = blockIdx.y, t = threadIdx.x;  // t < 96
    {
        int gate = t >> 5, jj = t & 31;
        int row = gate * HID + r * HPC + jj;
        g_wihcTh[(r * C_ + c) * 96 + t] = __float2half(wih[row * WIHC + c]);
        if (c < HID)
            g_whhT[(r * HID + c) * 96 + t] = whh[row * HID + c];
    }
    if (c < HID) {
        if (t < 32)
            g_h2hT4[((r * 64 + (c >> 2)) * 32 + t) * 4 + (c & 3)] =
                h2h_w[(r * HPC + t) * HID + c];
        if (t < 64) {
            int j = t & 31;
            float v = (t < 32) ? sg1_w[(r * HPC + j) * HID + c]
                               : lg1_w[(r * HPC + j) * HID + c];
            g_sglgT[((r * 64 + (c >> 2)) * 32 + j) * 8 + (t >> 5) * 4 + (c & 3)] =
                __float2half(v);
        }
    }
}

// ---------------- K0b: embedding fold ----------------
__global__ void emb_kernel(const float* __restrict__ wih, const float* __restrict__ bih) {
    int row = blockIdx.x;
    if (threadIdx.x < NE)
        g_emb[threadIdx.x * GRU3 + row] = wih[row * WIHC + C_ + threadIdx.x] + bih[row];
}

// ---------------- K1: h_proj = feat @ i2h_w^T ----------------
__global__ __launch_bounds__(256) void hproj_kernel(const float* __restrict__ fea,
                                                    const float* __restrict__ i2h_w) {
    __shared__ float sf[8 * C_];
    int b = blockIdx.y, nb = blockIdx.x * 8;
    for (int idx = threadIdx.x; idx < 8 * C_; idx += 256) {
        int q = idx >> 9, c = idx & (C_ - 1);
        sf[idx] = fea[(b * C_ + c) * NSP + nb + q];
    }
    __syncthreads();
    int h = threadIdx.x;
    float acc[8];
#pragma unroll
    for (int q = 0; q < 8; ++q) acc[q] = 0.f;
    const float4* w4 = reinterpret_cast<const float4*>(i2h_w + h * C_);
    for (int c4 = 0; c4 < C_ / 4; ++c4) {
        float4 wv = w4[c4];
#pragma unroll
        for (int q = 0; q < 8; ++q) {
            float4 sv = *reinterpret_cast<const float4*>(sf + q * C_ + c4 * 4);
            acc[q] = fmaf(wv.x, sv.x, acc[q]); acc[q] = fmaf(wv.y, sv.y, acc[q]);
            acc[q] = fmaf(wv.z, sv.z, acc[q]); acc[q] = fmaf(wv.w, sv.w, acc[q]);
        }
    }
#pragma unroll
    for (int q = 0; q < 8; ++q)
        g_hproj[(b * NSP + nb + q) * HID + h] = acc[q];
}

// ---------------- K2: persistent cluster decode ----------------
__global__ __cluster_dims__(CSZ, 1, 1) __launch_bounds__(NTHR, 1)
void decode_kernel(const float* __restrict__ fea,
                   const int*   __restrict__ structure,
                   const float* __restrict__ h2h_b,
                   const float* __restrict__ score_w,
                   const float* __restrict__ bhh,
                   const float* __restrict__ sg1_b,
                   const float* __restrict__ sg2_w, const float* __restrict__ sg2_b,
                   const float* __restrict__ lg1_b,
                   const float* __restrict__ lg2_w, const float* __restrict__ lg2_b,
                   float* __restrict__ out) {
    extern __shared__ char smraw[];
    SmemT* s = reinterpret_cast<SmemT*>(smraw);

    const int b = blockIdx.y;
    const int r = blockIdx.x;
    const int tid = threadIdx.x;
    const int lane = tid & 31;
    const int w = tid >> 5;   // 0..15

    // ---- preload resident tiles ----
    for (int idx = tid; idx < NPC * HID; idx += NTHR)
        s->hp[idx] = g_hproj[(b * NSP + r * NPC) * HID + idx];
    for (int idx = tid; idx < HID * 96; idx += NTHR)
        s->whhT[idx] = g_whhT[r * HID * 96 + idx];
    for (int idx = tid; idx < NE * HID; idx += NTHR)
        s->sg2s[idx] = sg2_w[idx];
    for (int idx = tid; idx < 8 * HID; idx += NTHR)
        s->lg2s[idx] = lg2_w[idx];
    for (int idx = tid; idx < T_; idx += NTHR)
        s->stok[idx] = structure[b * T_ + idx];
    if (tid < HID) {
        s->sw[tid] = score_w[tid];
        s->hidf[0][tid] = 0.f;
        s->hidf[1][tid] = 0.f;
    }
    if (tid < 96) {
        s->pb1[tid] = (tid < 32) ? h2h_b[r * HPC + tid]
                    : (tid < 64) ? sg1_b[r * HPC + tid - 32]
                                 : lg1_b[r * HPC + tid - 64];
        s->pbg[tid] = bhh[(tid >> 5) * HID + r * HPC + (tid & 31)];
    }
    __syncthreads();
    CLUSTER_SYNC();

    // hoisted attention score weights
    const float4* sw4 = reinterpret_cast<const float4*>(s->sw);
    const float4 swa = sw4[lane], swb = sw4[lane + 32];

    int cur = 0;
    for (int i = 0; i <= T_; ++i) {
        const float* hid = s->hidf[cur];

        // prefetch embedding biases for PH4 (consumed 3 phases later)
        float ebr = 0.f, ebz = 0.f, ebn = 0.f;
        if (i < T_ && tid < HPC) {
            const int ct = s->stok[i];
            const float* eb = g_emb + ct * GRU3 + r * HPC + tid;
            ebr = eb[0]; ebz = eb[HID]; ebn = eb[2 * HID];
        }

        // ===== PH1: pp + head-L1 via transposed weights (c-split over 16 warps) =====
        {
            float accp = 0.f, acc0 = 0.f, acc1 = 0.f;
            const float4* h2h4 = reinterpret_cast<const float4*>(g_h2hT4)
                                 + (r * 64 + w * 4) * 32 + lane;
            const uint4* sg4 = reinterpret_cast<const uint4*>(g_sglgT)
                               + (r * 64 + w * 4) * 32 + lane;
#pragma unroll
            for (int q = 0; q < 4; ++q) {
                float4 xv = *reinterpret_cast<const float4*>(hid + (w * 4 + q) * 4);
                float4 wv = h2h4[q * 32];
                accp = fmaf(wv.x, xv.x, accp); accp = fmaf(wv.y, xv.y, accp);
                accp = fmaf(wv.z, xv.z, accp); accp = fmaf(wv.w, xv.w, accp);
                uint4 sv = sg4[q * 32];
                float2 a0 = __half22float2(*reinterpret_cast<const __half2*>(&sv.x));
                float2 a1 = __half22float2(*reinterpret_cast<const __half2*>(&sv.y));
                float2 b0 = __half22float2(*reinterpret_cast<const __half2*>(&sv.z));
                float2 b1 = __half22float2(*reinterpret_cast<const __half2*>(&sv.w));
                acc0 = fmaf(a0.x, xv.x, acc0); acc0 = fmaf(a0.y, xv.y, acc0);
                acc0 = fmaf(a1.x, xv.z, acc0); acc0 = fmaf(a1.y, xv.w, acc0);
                acc1 = fmaf(b0.x, xv.x, acc1); acc1 = fmaf(b0.y, xv.y, acc1);
                acc1 = fmaf(b1.x, xv.z, acc1); acc1 = fmaf(b1.y, xv.w, acc1);
            }
            s->partA[w * 96 + lane]      = accp;   // pp partial, j=lane
            s->partA[w * 96 + 32 + lane] = acc0;   // sg1 partial
            s->partA[w * 96 + 64 + lane] = acc1;   // lg1 partial
        }
        __syncthreads();
        if (tid < 96) {
            float v = s->pb1[tid];
#pragma unroll
            for (int k = 0; k < NWRP; ++k) v += s->partA[k * 96 + tid];
            float* dst = (tid < 32) ? &s->ppf[r * HPC + tid]
                       : (tid < 64) ? &s->m1f[r * HPC + tid - 32]
                                    : &s->lm1f[r * HPC + tid - 64];
#pragma unroll
            for (int k = 0; k < CSZ; ++k) st_rank_(dst, k, v);
        }
        CLUSTER_SYNC();

        // ===== PH2: attention scores (i<T) + head-L2 output (i>=1) =====
        if (i < T_) {
            const float4* pp4 = reinterpret_cast<const float4*>(s->ppf);
            float4 ppa = pp4[lane], ppb = pp4[lane + 32];
            float wsum = 0.f;
            for (int nl = w; nl < NPC; nl += NWRP) {
                const float4* hp4 = reinterpret_cast<const float4*>(s->hp + nl * HID);
                float4 ha = hp4[lane], hb = hp4[lane + 32];
                float acc = 0.f;
                acc = fmaf(tanh_(ha.x + ppa.x), swa.x, acc);
                acc = fmaf(tanh_(ha.y + ppa.y), swa.y, acc);
                acc = fmaf(tanh_(ha.z + ppa.z), swa.z, acc);
                acc = fmaf(tanh_(ha.w + ppa.w), swa.w, acc);
                acc = fmaf(tanh_(hb.x + ppb.x), swb.x, acc);
                acc = fmaf(tanh_(hb.y + ppb.y), swb.y, acc);
                acc = fmaf(tanh_(hb.z + ppb.z), swb.z, acc);
                acc = fmaf(tanh_(hb.w + ppb.w), swb.w, acc);
                acc = wred_(acc);
                float ex = expf_(acc);
                push8_(&s->eexpf[r * NPC + nl], ex, lane);
                wsum += ex;
            }
            if (lane == 0) s->wredbuf[w] = wsum;
        }
        if (i >= 1) {
            int rid = w * 8 + r;
            if (rid < OUTD) {
                float val;
                if (rid < NE) {
                    val = wdot_<2>(s->sg2s + rid * HID, s->m1f, lane) + sg2_b[rid];
                } else {
                    int lr = rid - NE;
                    val = sigm_(wdot_<2>(s->lg2s + lr * HID, s->lm1f, lane) + lg2_b[lr]);
                }
                if (lane == 0) out[(b * T_ + (i - 1)) * OUTD + rid] = val;
            }
        }
        __syncthreads();
        if (i < T_ && tid == 0) {
            float ps = 0.f;
#pragma unroll
            for (int k = 0; k < NWRP; ++k) ps += s->wredbuf[k];
            for (int k = 0; k < CSZ; ++k) st_rank_(&s->esumf[r], k, ps);
        }
        CLUSTER_SYNC();

        // ===== PH3: softmax normalize + context (feat streamed from L2) =====
        if (i < T_) {
            float tot = 0.f;
#pragma unroll
            for (int k = 0; k < CSZ; ++k) tot += s->esumf[k];
            const float inv = 1.0f / tot;
            const float4* e4 = reinterpret_cast<const float4*>(s->eexpf);
            const float* fbase = fea + (b * C_ + r * CPC) * NSP;
            for (int cl = w; cl < CPC; cl += NWRP) {
                const float4* f4 = reinterpret_cast<const float4*>(fbase + cl * NSP);
                float acc = 0.f;
#pragma unroll
                for (int it = 0; it < 3; ++it) {
                    float4 fv = f4[lane + 32 * it];
                    float4 ev = e4[lane + 32 * it];
                    acc = fmaf(fv.x, ev.x, acc); acc = fmaf(fv.y, ev.y, acc);
                    acc = fmaf(fv.z, ev.z, acc); acc = fmaf(fv.w, ev.w, acc);
                }
                if (lane < 4) {
                    float4 fv = f4[96 + lane];
                    float4 ev = e4[96 + lane];
                    acc = fmaf(fv.x, ev.x, acc); acc = fmaf(fv.y, ev.y, acc);
                    acc = fmaf(fv.z, ev.z, acc); acc = fmaf(fv.w, ev.w, acc);
                }
                acc = wred_(acc);
                push8_(&s->ctxf[r * CPC + cl], acc * inv, lane);
            }
        }
        CLUSTER_SYNC();

        // ===== PH4: GRU (gi streamed f16 wihcT, gh resident whhT; 16 warps) =====
        if (i < T_) {
            if (lane < 24) {
                // gi: warp owns 32 ctx channels; lane owns g-outputs 4*lane..4*lane+3
                float4 ga = make_float4(0.f, 0.f, 0.f, 0.f);
                const uint2* wi2 = reinterpret_cast<const uint2*>(
                                       g_wihcTh + (r * C_ + w * 32) * 96) + lane;
#pragma unroll 4
                for (int c4 = 0; c4 < 8; ++c4) {
                    float4 xv = *reinterpret_cast<const float4*>(s->ctxf + w * 32 + c4 * 4);
                    uint2 v0 = wi2[(c4 * 4 + 0) * 24];
                    uint2 v1 = wi2[(c4 * 4 + 1) * 24];
                    uint2 v2 = wi2[(c4 * 4 + 2) * 24];
                    uint2 v3 = wi2[(c4 * 4 + 3) * 24];
                    float2 p0 = __half22float2(*reinterpret_cast<const __half2*>(&v0.x));
                    float2 p1 = __half22float2(*reinterpret_cast<const __half2*>(&v0.y));
                    ga.x = fmaf(p0.x, xv.x, ga.x); ga.y = fmaf(p0.y, xv.x, ga.y);
                    ga.z = fmaf(p1.x, xv.x, ga.z); ga.w = fmaf(p1.y, xv.x, ga.w);
                    p0 = __half22float2(*reinterpret_cast<const __half2*>(&v1.x));
                    p1 = __half22float2(*reinterpret_cast<const __half2*>(&v1.y));
                    ga.x = fmaf(p0.x, xv.y, ga.x); ga.y = fmaf(p0.y, xv.y, ga.y);
                    ga.z = fmaf(p1.x, xv.y, ga.z); ga.w = fmaf(p1.y, xv.y, ga.w);
                    p0 = __half22float2(*reinterpret_cast<const __half2*>(&v2.x));
                    p1 = __half22float2(*reinterpret_cast<const __half2*>(&v2.y));
                    ga.x = fmaf(p0.x, xv.z, ga.x); ga.y = fmaf(p0.y, xv.z, ga.y);
                    ga.z = fmaf(p1.x, xv.z, ga.z); ga.w = fmaf(p1.y, xv.z, ga.w);
                    p0 = __half22float2(*reinterpret_cast<const __half2*>(&v3.x));
                    p1 = __half22float2(*reinterpret_cast<const __half2*>(&v3.y));
                    ga.x = fmaf(p0.x, xv.w, ga.x); ga.y = fmaf(p0.y, xv.w, ga.y);
                    ga.z = fmaf(p1.x, xv.w, ga.z); ga.w = fmaf(p1.y, xv.w, ga.w);
                }
                *reinterpret_cast<float4*>(&s->partA[w * 96 + 4 * lane]) = ga;

                // gh: warp owns 16 hidden channels (resident whhT)
                float4 gb = make_float4(0.f, 0.f, 0.f, 0.f);
#pragma unroll 4
                for (int c4 = 0; c4 < 4; ++c4) {
                    float4 xv = *reinterpret_cast<const float4*>(hid + w * 16 + c4 * 4);
                    float4 w0 = *reinterpret_cast<const float4*>(&s->whhT[(w * 16 + c4 * 4 + 0) * 96 + 4 * lane]);
                    float4 w1 = *reinterpret_cast<const float4*>(&s->whhT[(w * 16 + c4 * 4 + 1) * 96 + 4 * lane]);
                    float4 w2 = *reinterpret_cast<const float4*>(&s->whhT[(w * 16 + c4 * 4 + 2) * 96 + 4 * lane]);
                    float4 w3 = *reinterpret_cast<const float4*>(&s->whhT[(w * 16 + c4 * 4 + 3) * 96 + 4 * lane]);
                    gb.x = fmaf(w0.x, xv.x, gb.x); gb.y = fmaf(w0.y, xv.x, gb.y);
                    gb.z = fmaf(w0.z, xv.x, gb.z); gb.w = fmaf(w0.w, xv.x, gb.w);
                    gb.x = fmaf(w1.x, xv.y, gb.x); gb.y = fmaf(w1.y, xv.y, gb.y);
                    gb.z = fmaf(w1.z, xv.y, gb.z); gb.w = fmaf(w1.w, xv.y, gb.w);
                    gb.x = fmaf(w2.x, xv.z, gb.x); gb.y = fmaf(w2.y, xv.z, gb.y);
                    gb.z = fmaf(w2.z, xv.z, gb.z); gb.w = fmaf(w2.w, xv.z, gb.w);
                    gb.x = fmaf(w3.x, xv.w, gb.x); gb.y = fmaf(w3.y, xv.w, gb.y);
                    gb.z = fmaf(w3.z, xv.w, gb.z); gb.w = fmaf(w3.w, xv.w, gb.w);
                }
                *reinterpret_cast<float4*>(&s->partB[w * 96 + 4 * lane]) = gb;
            }
            __syncthreads();
            if (tid < HPC) {
                float gir = 0.f, giz = 0.f, gin = 0.f, ghr = 0.f, ghz = 0.f, ghn = 0.f;
#pragma unroll
                for (int k = 0; k < NWRP; ++k) {
                    gir += s->partA[k * 96 + tid];
                    giz += s->partA[k * 96 + 32 + tid];
                    gin += s->partA[k * 96 + 64 + tid];
                    ghr += s->partB[k * 96 + tid];
                    ghz += s->partB[k * 96 + 32 + tid];
                    ghn += s->partB[k * 96 + 64 + tid];
                }
                gir += ebr;
                giz += ebz;
                gin += ebn;
                ghr += s->pbg[tid];
                ghz += s->pbg[32 + tid];
                ghn += s->pbg[64 + tid];
                float rr = sigm_(gir + ghr);
                float zz = sigm_(giz + ghz);
                float nn = tanh_(fmaf(rr, ghn, gin));
                float hn = fmaf(zz, hid[r * HPC + tid] - nn, nn);
                float* dst = &s->hidf[cur ^ 1][r * HPC + tid];
#pragma unroll
                for (int k = 0; k < CSZ; ++k) st_rank_(dst, k, hn);
            }
        }
        CLUSTER_SYNC();
        cur ^= 1;
    }
}

// ---------------- launch ----------------
extern "C" void kernel_launch(void* const* d_in, const int* in_sizes, int n_in,
                              void* d_out, int out_size) {
    const float* fea       = (const float*)d_in[0];
    const int*   structure = (const int*)  d_in[1];
    const float* i2h_w     = (const float*)d_in[2];
    const float* h2h_w     = (const float*)d_in[3];
    const float* h2h_b     = (const float*)d_in[4];
    const float* score_w   = (const float*)d_in[5];
    const float* gru_wih   = (const float*)d_in[6];
    const float* gru_bih   = (const float*)d_in[7];
    const float* gru_whh   = (const float*)d_in[8];
    const float* gru_bhh   = (const float*)d_in[9];
    const float* sg1_w     = (const float*)d_in[10];
    const float* sg1_b     = (const float*)d_in[11];
    const float* sg2_w     = (const float*)d_in[12];
    const float* sg2_b     = (const float*)d_in[13];
    const float* lg1_w     = (const float*)d_in[14];
    const float* lg1_b     = (const float*)d_in[15];
    const float* lg2_w     = (const float*)d_in[16];
    const float* lg2_b     = (const float*)d_in[17];
    float* out = (float*)d_out;

    cudaFuncSetAttribute(decode_kernel,
                         cudaFuncAttributeMaxDynamicSharedMemorySize, SMEM_BYTES);

    repackT_kernel<<<dim3(CSZ, C_), 96>>>(h2h_w, sg1_w, lg1_w, gru_whh, gru_wih);
    emb_kernel<<<GRU3, 32>>>(gru_wih, gru_bih);
    hproj_kernel<<<dim3(NSP / 8, B_), 256>>>(fea, i2h_w);
    decode_kernel<<<dim3(CSZ, B_), NTHR, SMEM_BYTES>>>(
        fea, structure, h2h_b, score_w, gru_bhh,
        sg1_b, sg2_w, sg2_b, lg1_b, lg2_w, lg2_b, out);
}